// round 6
// baseline (speedup 1.0000x reference)
#include <cuda_runtime.h>
#include <cuda_fp16.h>
#include <cuda_fp8.h>

#define N_NODES 100000
#define D_FEAT  128
#define MAX_E   600000
#define NB2     592      // fused kernel grid: exactly one wave (148 SMs x 4 CTAs)
#define NBC     1184     // convert grid: 8 CTAs/SM -> 64 warps/SM
#define TPB     256
#define MAXC    8192
#define MARGIN  12.0f    // >> worst-case fp8+half coarse-score error (~3.5)

// Scratch (static __device__ — no allocation allowed)
__device__ __align__(128) unsigned g_h8[N_NODES * D_FEAT / 4]; // e4m3 rows, 128B each
__device__ float    g_score[MAX_E];               // coarse per-edge scores (2.4 MB)
__device__ float    g_blockmin[NB2];
__device__ int      g_cand[MAXC];
__device__ float    g_cand_score[MAXC];
__device__ int      g_ncand;
__device__ int      g_bar;     // grid-barrier arrival counter
__device__ int      g_done;    // last-block election for rescore

__device__ __forceinline__ __half2 fp8x2_to_h2(unsigned short v) {
    __half2_raw r = __nv_cvt_fp8x2_to_halfraw2((__nv_fp8x2_storage_t)v, __NV_E4M3);
    return *reinterpret_cast<__half2*>(&r);
}

__device__ __forceinline__ unsigned f4_to_fp8x4(float4 f) {
    unsigned lo = __nv_cvt_float2_to_fp8x2(make_float2(f.x, f.y), __NV_SATFINITE, __NV_E4M3);
    unsigned hi = __nv_cvt_float2_to_fp8x2(make_float2(f.z, f.w), __NV_SATFINITE, __NV_E4M3);
    return lo | (hi << 16);
}

// K1: f32 -> e4m3 conversion of h. 4x float4 loads -> 1 uint4 store per iter
// for MLP + coalesced 16B writes. Also resets counters (runs first every call).
__global__ void convert_kernel(const float* __restrict__ h, int n16) {
    if (blockIdx.x == 0 && threadIdx.x == 0) { g_ncand = 0; g_bar = 0; g_done = 0; }
    const float4* __restrict__ h4 = (const float4*)h;
    uint4* __restrict__ o16 = (uint4*)g_h8;
    const int stride = gridDim.x * blockDim.x;
    for (int i = blockIdx.x * blockDim.x + threadIdx.x; i < n16; i += stride) {
        float4 f0 = h4[i * 4 + 0];
        float4 f1 = h4[i * 4 + 1];
        float4 f2 = h4[i * 4 + 2];
        float4 f3 = h4[i * 4 + 3];
        uint4 o;
        o.x = f4_to_fp8x4(f0);
        o.y = f4_to_fp8x4(f1);
        o.z = f4_to_fp8x4(f2);
        o.w = f4_to_fp8x4(f3);
        o16[i] = o;
    }
}

// K2 (fused, persistent single wave):
//   Phase A: coarse fp8 scores (8-lane group per edge) + per-block min.
//   Grid barrier (all 592 blocks resident by construction).
//   Phase B: gmin reduce, out=1 + candidate select, last-block exact rescore.
__global__ void __launch_bounds__(TPB, 4)
score_finalize_kernel(const float* __restrict__ h,
                      const int* __restrict__ src,
                      const int* __restrict__ dst,
                      float* __restrict__ out, int E) {
    __shared__ float sm[TPB / 32];
    __shared__ bool s_last;
    const int lane = threadIdx.x & 31;
    const int wid  = threadIdx.x >> 5;
    const int gl   = lane & 7;
    const int gid  = (blockIdx.x * blockDim.x + threadIdx.x) >> 3;
    const int nG   = (gridDim.x * blockDim.x) >> 3;
    const uint4* __restrict__ h8 = (const uint4*)g_h8;   // row = 8 x uint4 = 128B

    // ---- Phase A: coarse scoring ----
    float lmin = 3.4e38f;
    for (int e = gid; e < E; e += nG) {
        const int s = src[e];
        const int d = dst[e];
        uint4 ua = h8[(long long)s * 8 + gl];
        uint4 ub = h8[(long long)d * 8 + gl];
        __half2 acc = __float2half2_rn(0.f);
        const unsigned* pa = &ua.x;
        const unsigned* pb = &ub.x;
        #pragma unroll
        for (int j = 0; j < 4; j++) {
            unsigned a = pa[j], b = pb[j];
            acc = __hfma2(fp8x2_to_h2((unsigned short)(a & 0xFFFFu)),
                          fp8x2_to_h2((unsigned short)(b & 0xFFFFu)), acc);
            acc = __hfma2(fp8x2_to_h2((unsigned short)(a >> 16)),
                          fp8x2_to_h2((unsigned short)(b >> 16)), acc);
        }
        float facc = __low2float(acc) + __high2float(acc);
        #pragma unroll
        for (int off = 4; off; off >>= 1)
            facc += __shfl_xor_sync(0xFFFFFFFFu, facc, off);
        if (gl == 0) g_score[e] = facc;
        lmin = fminf(lmin, facc);
    }

    #pragma unroll
    for (int off = 16; off; off >>= 1)
        lmin = fminf(lmin, __shfl_xor_sync(0xFFFFFFFFu, lmin, off));
    if (lane == 0) sm[wid] = lmin;
    __syncthreads();
    if (threadIdx.x == 0) {
        float m = sm[0];
        #pragma unroll
        for (int i = 1; i < TPB / 32; i++) m = fminf(m, sm[i]);
        g_blockmin[blockIdx.x] = m;
    }

    // ---- Grid barrier (safe: NB2 = one full wave, all blocks resident) ----
    __threadfence();
    __syncthreads();
    if (threadIdx.x == 0) {
        atomicAdd(&g_bar, 1);
        while (*(volatile int*)&g_bar < (int)gridDim.x) __nanosleep(64);
    }
    __syncthreads();

    // ---- Phase B: gmin, out=1, candidate select ----
    float m = 3.4e38f;
    for (int i = threadIdx.x; i < NB2; i += blockDim.x)
        m = fminf(m, g_blockmin[i]);
    #pragma unroll
    for (int off = 16; off; off >>= 1)
        m = fminf(m, __shfl_xor_sync(0xFFFFFFFFu, m, off));
    if (lane == 0) sm[wid] = m;
    __syncthreads();
    float gmin = sm[0];
    #pragma unroll
    for (int i = 1; i < TPB / 32; i++) gmin = fminf(gmin, sm[i]);
    __syncthreads();   // sm[] reused below

    const int nth = gridDim.x * blockDim.x;
    for (int e = blockIdx.x * blockDim.x + threadIdx.x; e < E; e += nth) {
        out[e] = 1.0f;
        if (g_score[e] <= gmin + MARGIN) {
            int idx = atomicAdd(&g_ncand, 1);
            if (idx < MAXC) g_cand[idx] = e;
        }
    }

    // ---- Last block: exact fp32 rescore of candidates, mark true min ----
    __threadfence();
    if (threadIdx.x == 0) {
        int t = atomicAdd(&g_done, 1);
        s_last = (t == (int)gridDim.x - 1);
    }
    __syncthreads();
    if (!s_last) return;

    const int nc = min(g_ncand, MAXC);
    float wmin = 3.4e38f;
    for (int i = wid; i < nc; i += TPB / 32) {     // warp per candidate
        const int ce = g_cand[i];
        float4 a = ((const float4*)(h + (long long)src[ce] * D_FEAT))[lane];
        float4 b = ((const float4*)(h + (long long)dst[ce] * D_FEAT))[lane];
        float acc = a.x * b.x + a.y * b.y + a.z * b.z + a.w * b.w;
        #pragma unroll
        for (int off = 16; off; off >>= 1)
            acc += __shfl_xor_sync(0xFFFFFFFFu, acc, off);
        if (lane == 0) g_cand_score[i] = acc;
        wmin = fminf(wmin, acc);
    }
    if (lane == 0) sm[wid] = wmin;
    __syncthreads();
    float gm = sm[0];
    #pragma unroll
    for (int i = 1; i < TPB / 32; i++) gm = fminf(gm, sm[i]);

    for (int i = threadIdx.x; i < nc; i += blockDim.x)
        if (g_cand_score[i] == gm) out[g_cand[i]] = 0.0f;
}

extern "C" void kernel_launch(void* const* d_in, const int* in_sizes, int n_in,
                              void* d_out, int out_size) {
    const float* h   = (const float*)d_in[0];
    const int*   src = (const int*)d_in[1];
    const int*   dst = (const int*)d_in[2];
    float* out = (float*)d_out;

    const int E   = in_sizes[1];
    const int n16 = N_NODES * D_FEAT / 16;   // uint4 outputs

    convert_kernel<<<NBC, TPB>>>(h, n16);
    score_finalize_kernel<<<NB2, TPB>>>(h, src, dst, out, E);
}

// round 7
// speedup vs baseline: 1.0462x; 1.0462x over previous
#include <cuda_runtime.h>
#include <cuda_fp16.h>
#include <cuda_fp8.h>

#define N_NODES 100000
#define D_FEAT  128
#define MAX_E   600000
#define NB2     888      // fused kernel grid: one wave at 6 CTAs/SM (148*6)
#define NBC     1184     // convert grid
#define TPB     256
#define MAXC    8192
#define MARGIN  12.0f    // >> worst-case fp8+half coarse-score error (~3.5)

// Scratch (static __device__ — no allocation allowed)
__device__ __align__(128) unsigned g_h8[N_NODES * D_FEAT / 4]; // e4m3 rows, 128B each
__device__ float    g_score[MAX_E];               // coarse per-edge scores (2.4 MB)
__device__ float    g_blockmin[NB2];
__device__ int      g_cand[MAXC];
__device__ float    g_cand_score[MAXC];
__device__ int      g_ncand;
__device__ int      g_bar;     // grid-barrier arrival counter
__device__ int      g_done;    // last-block election for rescore

__device__ __forceinline__ __half2 fp8x2_to_h2(unsigned short v) {
    __half2_raw r = __nv_cvt_fp8x2_to_halfraw2((__nv_fp8x2_storage_t)v, __NV_E4M3);
    return *reinterpret_cast<__half2*>(&r);
}

__device__ __forceinline__ unsigned f4_to_fp8x4(float4 f) {
    unsigned lo = __nv_cvt_float2_to_fp8x2(make_float2(f.x, f.y), __NV_SATFINITE, __NV_E4M3);
    unsigned hi = __nv_cvt_float2_to_fp8x2(make_float2(f.z, f.w), __NV_SATFINITE, __NV_E4M3);
    return lo | (hi << 16);
}

// fp8 row-pair dot, accumulated in half2 then reduced to float.
__device__ __forceinline__ float dot_fp8_16B(uint4 ua, uint4 ub) {
    __half2 acc = __float2half2_rn(0.f);
    const unsigned* pa = &ua.x;
    const unsigned* pb = &ub.x;
    #pragma unroll
    for (int j = 0; j < 4; j++) {
        unsigned a = pa[j], b = pb[j];
        acc = __hfma2(fp8x2_to_h2((unsigned short)(a & 0xFFFFu)),
                      fp8x2_to_h2((unsigned short)(b & 0xFFFFu)), acc);
        acc = __hfma2(fp8x2_to_h2((unsigned short)(a >> 16)),
                      fp8x2_to_h2((unsigned short)(b >> 16)), acc);
    }
    return __low2float(acc) + __high2float(acc);
}

// K1: f32 -> e4m3 conversion of h. 4x float4 loads -> 1 uint4 store per iter.
// Also resets counters (runs first every call -> graph-replay deterministic).
__global__ void convert_kernel(const float* __restrict__ h, int n16) {
    if (blockIdx.x == 0 && threadIdx.x == 0) { g_ncand = 0; g_bar = 0; g_done = 0; }
    const float4* __restrict__ h4 = (const float4*)h;
    uint4* __restrict__ o16 = (uint4*)g_h8;
    const int stride = gridDim.x * blockDim.x;
    for (int i = blockIdx.x * blockDim.x + threadIdx.x; i < n16; i += stride) {
        float4 f0 = h4[i * 4 + 0];
        float4 f1 = h4[i * 4 + 1];
        float4 f2 = h4[i * 4 + 2];
        float4 f3 = h4[i * 4 + 3];
        uint4 o;
        o.x = f4_to_fp8x4(f0);
        o.y = f4_to_fp8x4(f1);
        o.z = f4_to_fp8x4(f2);
        o.w = f4_to_fp8x4(f3);
        o16[i] = o;
    }
}

// K2 (fused, persistent single wave, 6 CTAs/SM):
//   Phase A: coarse fp8 scores, 2 edges in flight per 8-lane group (MLP 4).
//   Grid barrier (all 888 blocks resident by construction).
//   Phase B: gmin reduce, out=1 + candidate select, last-block exact rescore.
__global__ void __launch_bounds__(TPB, 6)
score_finalize_kernel(const float* __restrict__ h,
                      const int* __restrict__ src,
                      const int* __restrict__ dst,
                      float* __restrict__ out, int E) {
    __shared__ float sm[TPB / 32];
    __shared__ bool s_last;
    const int lane = threadIdx.x & 31;
    const int wid  = threadIdx.x >> 5;
    const unsigned gl = lane & 7;
    const int gid  = (blockIdx.x * blockDim.x + threadIdx.x) >> 3;
    const int nG   = (gridDim.x * blockDim.x) >> 3;
    const uint4* __restrict__ h8 = (const uint4*)g_h8;   // row = 8 x uint4 = 128B

    // ---- Phase A: coarse scoring, 2 edges per iteration ----
    float lmin = 3.4e38f;
    for (int e = gid; e < E; e += 2 * nG) {
        const int e2 = e + nG;
        const bool has2 = (e2 < E);
        // All index loads + all gathers issued before any consumption (MLP).
        const unsigned s0 = (unsigned)src[e];
        const unsigned d0 = (unsigned)dst[e];
        const unsigned s1 = has2 ? (unsigned)src[e2] : s0;
        const unsigned d1 = has2 ? (unsigned)dst[e2] : d0;
        uint4 ua0 = h8[s0 * 8u + gl];
        uint4 ub0 = h8[d0 * 8u + gl];
        uint4 ua1 = h8[s1 * 8u + gl];
        uint4 ub1 = h8[d1 * 8u + gl];

        float f0 = dot_fp8_16B(ua0, ub0);
        float f1 = dot_fp8_16B(ua1, ub1);
        #pragma unroll
        for (int off = 4; off; off >>= 1) {
            f0 += __shfl_xor_sync(0xFFFFFFFFu, f0, off);
            f1 += __shfl_xor_sync(0xFFFFFFFFu, f1, off);
        }
        if (gl == 0) {
            g_score[e] = f0;
            if (has2) g_score[e2] = f1;
        }
        lmin = fminf(lmin, f0);
        if (has2) lmin = fminf(lmin, f1);
    }

    #pragma unroll
    for (int off = 16; off; off >>= 1)
        lmin = fminf(lmin, __shfl_xor_sync(0xFFFFFFFFu, lmin, off));
    if (lane == 0) sm[wid] = lmin;
    __syncthreads();
    if (threadIdx.x == 0) {
        float m = sm[0];
        #pragma unroll
        for (int i = 1; i < TPB / 32; i++) m = fminf(m, sm[i]);
        g_blockmin[blockIdx.x] = m;
    }

    // ---- Grid barrier (safe: NB2 = one full wave, all blocks resident) ----
    __threadfence();
    __syncthreads();
    if (threadIdx.x == 0) {
        atomicAdd(&g_bar, 1);
        while (*(volatile int*)&g_bar < (int)gridDim.x) __nanosleep(64);
    }
    __syncthreads();

    // ---- Phase B: gmin, out=1, candidate select ----
    float m = 3.4e38f;
    for (int i = threadIdx.x; i < NB2; i += blockDim.x)
        m = fminf(m, g_blockmin[i]);
    #pragma unroll
    for (int off = 16; off; off >>= 1)
        m = fminf(m, __shfl_xor_sync(0xFFFFFFFFu, m, off));
    if (lane == 0) sm[wid] = m;
    __syncthreads();
    float gmin = sm[0];
    #pragma unroll
    for (int i = 1; i < TPB / 32; i++) gmin = fminf(gmin, sm[i]);
    __syncthreads();   // sm[] reused below

    const int nth = gridDim.x * blockDim.x;
    for (int e = blockIdx.x * blockDim.x + threadIdx.x; e < E; e += nth) {
        out[e] = 1.0f;
        if (g_score[e] <= gmin + MARGIN) {
            int idx = atomicAdd(&g_ncand, 1);
            if (idx < MAXC) g_cand[idx] = e;
        }
    }

    // ---- Last block: exact fp32 rescore of candidates, mark true min ----
    __threadfence();
    if (threadIdx.x == 0) {
        int t = atomicAdd(&g_done, 1);
        s_last = (t == (int)gridDim.x - 1);
    }
    __syncthreads();
    if (!s_last) return;

    const int nc = min(g_ncand, MAXC);
    float wmin = 3.4e38f;
    for (int i = wid; i < nc; i += TPB / 32) {     // warp per candidate
        const int ce = g_cand[i];
        float4 a = ((const float4*)(h + (long long)src[ce] * D_FEAT))[lane];
        float4 b = ((const float4*)(h + (long long)dst[ce] * D_FEAT))[lane];
        float acc = a.x * b.x + a.y * b.y + a.z * b.z + a.w * b.w;
        #pragma unroll
        for (int off = 16; off; off >>= 1)
            acc += __shfl_xor_sync(0xFFFFFFFFu, acc, off);
        if (lane == 0) g_cand_score[i] = acc;
        wmin = fminf(wmin, acc);
    }
    if (lane == 0) sm[wid] = wmin;
    __syncthreads();
    float gm = sm[0];
    #pragma unroll
    for (int i = 1; i < TPB / 32; i++) gm = fminf(gm, sm[i]);

    for (int i = threadIdx.x; i < nc; i += blockDim.x)
        if (g_cand_score[i] == gm) out[g_cand[i]] = 0.0f;
}

extern "C" void kernel_launch(void* const* d_in, const int* in_sizes, int n_in,
                              void* d_out, int out_size) {
    const float* h   = (const float*)d_in[0];
    const int*   src = (const int*)d_in[1];
    const int*   dst = (const int*)d_in[2];
    float* out = (float*)d_out;

    const int E   = in_sizes[1];
    const int n16 = N_NODES * D_FEAT / 16;   // uint4 outputs

    convert_kernel<<<NBC, TPB>>>(h, n16);
    score_finalize_kernel<<<NB2, TPB>>>(h, src, dst, out, E);
}